// round 2
// baseline (speedup 1.0000x reference)
#include <cuda_runtime.h>

// QLinear: out[B, OUT] = x[B, IN] @ expquantize(weight[OUT, IN]).T + expquantize(bias[OUT])
// B=8192, IN=4096, OUT=4096, all fp32.
//
// Key insight: weight/bias are scaled by 0.02, and expquantize(n=2) zeroes any
// value whose power-of-two snap is < 0.25 (i.e. |w| < 2^-2.5 = 0.1768 = 8.8 sigma).
// In practice the quantized weight matrix is ALL ZEROS, so the output is just a
// broadcast of the (also all-zero) quantized bias. We still do this fully
// correctly for arbitrary inputs: quantize everything, collect survivors into a
// sparse list, scatter them, with a dense fallback if the list overflows.

#define OUT_DIM 4096
#define IN_DIM  4096
#define B_DIM   8192
#define CAP     (1 << 20)   // sparse-entry capacity (never approached in practice)

struct Entry { int r; int c; float v; };

__device__ Entry g_entries[CAP];
__device__ int   g_nnz;
__device__ float g_bq[OUT_DIM];

// expquantize(x, n=2) without MUFU (log2f/exp2f would be the chip bottleneck:
// 33.5M MUFU ops ~ 250us). Result is one of {0, +-0.25, +-0.5, +-1}, decided by
// threshold comparison against the exact half-exponent boundaries.
// round(log2 a) >= -2  <=>  a >= 2^-2.5 ;  = -1 <=> a >= 2^-1.5 ; = 0 <=> a >= 2^-0.5.
// Tie/rounding discrepancies vs jnp's fp32 log2 + banker's round can only matter
// within a few ULP of the boundaries >= 0.1768 (8.8+ sigma: no samples), and every
// branch below 0.1768 maps to 0 either way.
__device__ __forceinline__ float expq(float x) {
    float a = fabsf(fminf(fmaxf(x, -1.0f), 1.0f));
    float q;
    if      (a >= 0.70710678118654752f) q = 1.0f;    // 2^-0.5
    else if (a >= 0.35355339059327376f) q = 0.5f;    // 2^-1.5
    else if (a >= 0.17677669529663689f) q = 0.25f;   // 2^-2.5
    else return 0.0f;
    return copysignf(q, x);
}

// Reset nnz counter + quantize bias into g_bq.
__global__ void k_reset(const float* __restrict__ bias) {
    int i = blockIdx.x * blockDim.x + threadIdx.x;
    if (i == 0) g_nnz = 0;
    if (i < OUT_DIM) g_bq[i] = expq(bias[i]);
}

// Quantize all weights (float4 streaming read, 64 MB). Append any survivors.
__global__ void k_quant(const float4* __restrict__ w4) {
    const int n4 = (OUT_DIM * IN_DIM) / 4;
    int stride = gridDim.x * blockDim.x;
    for (int i = blockIdx.x * blockDim.x + threadIdx.x; i < n4; i += stride) {
        float4 w = w4[i];
        float q0 = expq(w.x), q1 = expq(w.y), q2 = expq(w.z), q3 = expq(w.w);
        if (q0 != 0.0f || q1 != 0.0f || q2 != 0.0f || q3 != 0.0f) {
            float qs[4] = {q0, q1, q2, q3};
            int base = i * 4;
            #pragma unroll
            for (int k = 0; k < 4; k++) {
                if (qs[k] != 0.0f) {
                    int idx = atomicAdd(&g_nnz, 1);
                    if (idx < CAP) {
                        int e = base + k;
                        g_entries[idx].r = e >> 12;          // / IN_DIM
                        g_entries[idx].c = e & (IN_DIM - 1); // % IN_DIM
                        g_entries[idx].v = qs[k];
                    }
                }
            }
        }
    }
}

// Broadcast quantized bias into the output (128 MB write, float4).
__global__ void k_fill(float4* __restrict__ out4) {
    const int n4 = (B_DIM * OUT_DIM) / 4;
    const float4* bq4 = reinterpret_cast<const float4*>(g_bq);
    int stride = gridDim.x * blockDim.x;
    for (int i = blockIdx.x * blockDim.x + threadIdx.x; i < n4; i += stride) {
        out4[i] = bq4[i & (OUT_DIM / 4 - 1)];
    }
}

// Scatter sparse survivors: out[b][r] += v * x[b][c].
// nnz==0 -> immediate exit. Overflow (>CAP, practically impossible) -> dense
// re-scan fallback: slow but correct.
__global__ void k_scatter(const float* __restrict__ x,
                          const float* __restrict__ w,
                          float* __restrict__ out) {
    int nnz = g_nnz;
    long stride = (long)gridDim.x * blockDim.x;
    long gtid   = (long)blockIdx.x * blockDim.x + threadIdx.x;
    if (nnz <= CAP) {
        long total = (long)nnz * B_DIM;
        for (long t = gtid; t < total; t += stride) {
            int e = (int)(t >> 13);           // / B_DIM
            int b = (int)(t & (B_DIM - 1));   // % B_DIM
            Entry en = g_entries[e];
            atomicAdd(&out[(long)b * OUT_DIM + en.r], en.v * x[(long)b * IN_DIM + en.c]);
        }
    } else {
        // Dense fallback: re-quantize every weight on the fly.
        long nW = (long)OUT_DIM * IN_DIM;
        for (long t = gtid; t < nW; t += stride) {
            float q = expq(w[t]);
            if (q != 0.0f) {
                int r = (int)(t >> 12);
                int c = (int)(t & (IN_DIM - 1));
                for (int b = 0; b < B_DIM; b++)
                    atomicAdd(&out[(long)b * OUT_DIM + r], q * x[(long)b * IN_DIM + c]);
            }
        }
    }
}

extern "C" void kernel_launch(void* const* d_in, const int* in_sizes, int n_in,
                              void* d_out, int out_size) {
    const float* x    = (const float*)d_in[0];   // [8192, 4096]
    const float* w    = (const float*)d_in[1];   // [4096, 4096]
    const float* bias = (const float*)d_in[2];   // [4096]
    float* out = (float*)d_out;                  // [8192, 4096]

    k_reset  <<<(OUT_DIM + 255) / 256, 256>>>(bias);
    k_quant  <<<1184, 256>>>((const float4*)w);        // 148 SMs * 8
    k_fill   <<<2368, 256>>>((float4*)out);            // 148 SMs * 16
    k_scatter<<<256, 256>>>(x, w, out);
}

// round 7
// speedup vs baseline: 1.0513x; 1.0513x over previous
#include <cuda_runtime.h>

// QLinear: out[B, OUT] = x[B, IN] @ expquantize(weight[OUT, IN]).T + expquantize(bias[OUT])
// B=8192, IN=4096, OUT=4096, all fp32.
//
// expquantize(n=2) zeroes any value whose power-of-two snap is < 0.25
// (|w| < 2^-2.5 = 0.1768 = 8.8 sigma at the 0.02 scale) -> quantized weight
// and bias are all zeros in practice. We still stay correct for arbitrary
// inputs: quantize everything, collect survivors into a sparse list, and
// apply them in the output-fill kernel (dense fallback on overflow).
//
// 3 launches:
//   k_reset        : nnz=0, bias quantize            (~2 us)
//   k_quant        : 64 MB streaming read             (~11 us)
//   k_fill_scatter : 128 MB streaming write + sparse  (~21 us)
// Floor = 192 MB / ~6.8 TB/s ~ 28 us + launch overhead.

#define OUT_DIM 4096
#define IN_DIM  4096
#define B_DIM   8192
#define CAP     (1 << 20)   // sparse-entry capacity (never approached)

struct Entry { int r; int c; float v; };

__device__ Entry g_entries[CAP];
__device__ int   g_nnz;
__device__ float g_bq[OUT_DIM];

// expquantize(x, n=2) via threshold compares (no MUFU: log2f/exp2f x 33.5M
// elements would cost ~250us chip-wide). Result in {0, +-0.25, +-0.5, +-1}.
// Boundary-ULP discrepancies vs jnp's log2+round only possible at >=8.8 sigma
// magnitudes, which don't occur; everything below 0.1768 -> 0 on both paths.
__device__ __forceinline__ float expq(float x) {
    float a = fabsf(fminf(fmaxf(x, -1.0f), 1.0f));
    float q;
    if      (a >= 0.70710678118654752f) q = 1.0f;    // 2^-0.5
    else if (a >= 0.35355339059327376f) q = 0.5f;    // 2^-1.5
    else if (a >= 0.17677669529663689f) q = 0.25f;   // 2^-2.5
    else return 0.0f;
    return copysignf(q, x);
}

// Reset nnz counter + quantize bias into g_bq.
__global__ void k_reset(const float* __restrict__ bias) {
    int i = blockIdx.x * blockDim.x + threadIdx.x;
    if (i == 0) g_nnz = 0;
    if (i < OUT_DIM) g_bq[i] = expq(bias[i]);
}

// Quantize all weights (streaming float4 read, 64 MB). Append survivors.
__global__ void k_quant(const float4* __restrict__ w4) {
    const int n4 = (OUT_DIM * IN_DIM) / 4;
    int stride = gridDim.x * blockDim.x;
    for (int i = blockIdx.x * blockDim.x + threadIdx.x; i < n4; i += stride) {
        float4 w = __ldcs(&w4[i]);   // no reuse: stream past L2
        float q0 = expq(w.x), q1 = expq(w.y), q2 = expq(w.z), q3 = expq(w.w);
        if (q0 != 0.0f || q1 != 0.0f || q2 != 0.0f || q3 != 0.0f) {
            float qs[4] = {q0, q1, q2, q3};
            int base = i * 4;
            #pragma unroll
            for (int k = 0; k < 4; k++) {
                if (qs[k] != 0.0f) {
                    int idx = atomicAdd(&g_nnz, 1);
                    if (idx < CAP) {
                        int e = base + k;
                        g_entries[idx].r = e >> 12;          // / IN_DIM
                        g_entries[idx].c = e & (IN_DIM - 1); // % IN_DIM
                        g_entries[idx].v = qs[k];
                    }
                }
            }
        }
    }
}

// Fused fill + sparse scatter. Each thread owns float4 output groups.
// nnz==0 (the real case): pure 128 MB streaming bias-broadcast write.
// 0<nnz<=CAP: per output group, scan the entry list for row matches (O(nnz)
//   per thread -- fine for tiny nnz, correct always).
// nnz>CAP (overflow, never happens): dense on-the-fly requantized dot product.
__global__ void k_fill_scatter(const float* __restrict__ x,
                               const float* __restrict__ w,
                               float4* __restrict__ out4) {
    const int n4 = (B_DIM * OUT_DIM) / 4;
    const int og_per_row = OUT_DIM / 4;          // 1024
    int nnz = g_nnz;
    int stride = gridDim.x * blockDim.x;

    if (nnz == 0) {
        const float4* bq4 = reinterpret_cast<const float4*>(g_bq);
        for (int i = blockIdx.x * blockDim.x + threadIdx.x; i < n4; i += stride) {
            float4 v = bq4[i & (og_per_row - 1)];
            __stcs(&out4[i], v);                 // streaming store, no read-back
        }
        return;
    }

    if (nnz <= CAP) {
        const float4* bq4 = reinterpret_cast<const float4*>(g_bq);
        for (int i = blockIdx.x * blockDim.x + threadIdx.x; i < n4; i += stride) {
            int b  = i >> 10;                    // / og_per_row
            int og = i & (og_per_row - 1);
            float4 v = bq4[og];
            const float* xb = x + (long)b * IN_DIM;
            for (int e = 0; e < nnz; e++) {
                Entry en = g_entries[e];
                if ((en.r >> 2) == og) {
                    float add = en.v * xb[en.c];
                    switch (en.r & 3) {
                        case 0: v.x += add; break;
                        case 1: v.y += add; break;
                        case 2: v.z += add; break;
                        default: v.w += add; break;
                    }
                }
            }
            __stcs(&out4[i], v);
        }
        return;
    }

    // Overflow fallback: fully dense, requantize weights on the fly. Slow but
    // correct; unreachable for any plausible input.
    for (int i = blockIdx.x * blockDim.x + threadIdx.x; i < n4; i += stride) {
        int b  = i >> 10;
        int og = i & (og_per_row - 1);
        const float* xb = x + (long)b * IN_DIM;
        float acc[4];
        #pragma unroll
        for (int k = 0; k < 4; k++) {
            int o = og * 4 + k;
            float s = g_bq[o];
            const float* wr = w + (long)o * IN_DIM;
            for (int c = 0; c < IN_DIM; c++) {
                float q = expq(wr[c]);
                if (q != 0.0f) s += q * xb[c];
            }
            acc[k] = s;
        }
        __stcs(&out4[i], make_float4(acc[0], acc[1], acc[2], acc[3]));
    }
}

extern "C" void kernel_launch(void* const* d_in, const int* in_sizes, int n_in,
                              void* d_out, int out_size) {
    const float* x    = (const float*)d_in[0];   // [8192, 4096]
    const float* w    = (const float*)d_in[1];   // [4096, 4096]
    const float* bias = (const float*)d_in[2];   // [4096]

    k_reset       <<<(OUT_DIM + 255) / 256, 256>>>(bias);
    k_quant       <<<1184, 256>>>((const float4*)w);          // 148 SMs * 8
    k_fill_scatter<<<2368, 256>>>(x, w, (float4*)d_out);      // 148 SMs * 16
}